// round 17
// baseline (speedup 1.0000x reference)
#include <cuda_runtime.h>
#include <cuda_bf16.h>

#define BB 8
#define SS 1024
#define HH 8
#define EE 64
#define NBH (BB*HH)
#define NTOK (BB*SS)

typedef unsigned long long u64;
typedef unsigned int u32;

__device__ __align__(16) float g_attn[NTOK * EE];   // 2 MB scratch

// ---------------------------------------------------------------------------
// helpers
// ---------------------------------------------------------------------------
__device__ __forceinline__ u64 pk2(float lo, float hi) {
    u64 r; asm("mov.b64 %0, {%1, %2};" : "=l"(r) : "f"(lo), "f"(hi)); return r;
}
__device__ __forceinline__ u64 pfma(u64 a, u64 b, u64 c) {
    u64 d; asm("fma.rn.f32x2 %0, %1, %2, %3;" : "=l"(d) : "l"(a), "l"(b), "l"(c)); return d;
}
// round fp32 -> tf32 (rna); build phase only
__device__ __forceinline__ u32 cvt_tf32(float f) {
    u32 r; asm("cvt.rna.tf32.f32 %0, %1;" : "=r"(r) : "f"(f)); return r;
}
// pack two fp32 -> f16x2 (first arg -> HIGH half)
__device__ __forceinline__ u32 pkf16(float hi, float lo) {
    u32 r; asm("cvt.rn.f16x2.f32 %0, %1, %2;" : "=r"(r) : "f"(hi), "f"(lo)); return r;
}
// packed exp2 on two f16 lanes (ONE MUFU op, two exps)
__device__ __forceinline__ u32 ex2h2(u32 x) {
    u32 y; asm("ex2.approx.f16x2 %0, %1;" : "=r"(y) : "r"(x)); return y;
}

// m16n8k8 row.col tf32 MMA, fp32 accum
#define MMA_TF32(d0,d1,d2,d3, a0,a1,a2,a3, b0,b1, c0,c1,c2,c3) \
  asm volatile("mma.sync.aligned.m16n8k8.row.col.f32.tf32.tf32.f32 " \
    "{%0,%1,%2,%3}, {%4,%5,%6,%7}, {%8,%9}, {%10,%11,%12,%13};" \
    : "=f"(d0),"=f"(d1),"=f"(d2),"=f"(d3) \
    : "r"(a0),"r"(a1),"r"(a2),"r"(a3), "r"(b0),"r"(b1), \
      "f"(c0),"f"(c1),"f"(c2),"f"(c3))

// m16n8k16 row.col f16 MMA, fp32 accum
#define MMA_F16(d0,d1,d2,d3, a0,a1,a2,a3, b0,b1, c0,c1,c2,c3) \
  asm volatile("mma.sync.aligned.m16n8k16.row.col.f32.f16.f16.f32 " \
    "{%0,%1,%2,%3}, {%4,%5,%6,%7}, {%8,%9}, {%10,%11,%12,%13};" \
    : "=f"(d0),"=f"(d1),"=f"(d2),"=f"(d3) \
    : "r"(a0),"r"(a1),"r"(a2),"r"(a3), "r"(b0),"r"(b1), \
      "f"(c0),"f"(c1),"f"(c2),"f"(c3))

#define ONES_F16X2 0x3C003C00u

// ---------------------------------------------------------------------------
// Fused proj + attention. CTA = (bh, qtile 256), 512 thr.
// skf[1024][12]: tf32 key plane (score Q/B, conflict-free stride 12)
// vT[8][516]:   f16x2 transposed V (feature-major; word p = keys 2p,2p+1)
// Per 16 keys: 2 tf32 score MMAs -> 4 cvt.f16x2 + 4 ex2.f16x2 (2 exps/MUFU op)
// -> packed weights ARE the f16 m16n8k16 A-fragment -> 1 AV MMA + 1 den MMA.
// Denominator = sum of the SAME f16 weights (exact x1 products, fp32 accum).
// ---------------------------------------------------------------------------
#define KSTRIDE 12
#define VSTRIDE 516
#define SKF_WORDS (SS * KSTRIDE)                  // 12288 u32
#define ATTN_SMEM_BYTES ((SKF_WORDS + 8 * VSTRIDE) * 4)   // 65664

__global__ __launch_bounds__(512, 2) void attn_fused(const float* __restrict__ x,
                                                     const float* __restrict__ theta) {
    extern __shared__ __align__(16) u32 smu[];
    float* skf = (float*)smu;                 // [1024][12] tf32 floats
    u32*   vT  = smu + SKF_WORDS;             // [8][516] f16x2

    int bh = blockIdx.x;
    int b = bh >> 3, h = bh & 7;
    int qt = blockIdx.y;
    int tid = threadIdx.x;

    float th[8];
#pragma unroll
    for (int i = 0; i < 8; i++) th[i] = __ldg(&theta[i]);

    // ---------------- build phase: keys 2*tid, 2*tid+1 ----------------
    const float* xb = x + (size_t)(b * SS) * 64 + h * 8;
    float pv[2][8];
#pragma unroll
    for (int j = 0; j < 2; j++) {
        int s = tid * 2 + j;
        const float4* xs = (const float4*)(xb + (size_t)s * 64);
        float4 v0 = xs[0], v1 = xs[1];
        float a[8] = {v0.x, v0.y, v0.z, v0.w, v1.x, v1.y, v1.z, v1.w};
        float c[8];
#pragma unroll
        for (int i = 0; i < 8; i++) c[i] = __cosf(a[i] + th[i]);
        float* p = pv[j];
        p[1] = c[0] * c[1];
#pragma unroll
        for (int w = 2; w < 8; w++) p[w] = p[w - 1] * c[w];
        float qq = c[1];
#pragma unroll
        for (int i = 2; i < 8; i++) qq *= c[i];
        p[0] = qq;
        uint4 w0, w1;
        w0.x = cvt_tf32(p[0]); w0.y = cvt_tf32(p[1]);
        w0.z = cvt_tf32(p[2]); w0.w = cvt_tf32(p[3]);
        w1.x = cvt_tf32(p[4]); w1.y = cvt_tf32(p[5]);
        w1.z = cvt_tf32(p[6]); w1.w = cvt_tf32(p[7]);
        uint4* dst = (uint4*)(skf + s * KSTRIDE);
        dst[0] = w0; dst[1] = w1;
    }
    // transposed f16 V tile: vT[f][tid] = (f16(p_even[f]), f16(p_odd[f]))
#pragma unroll
    for (int f = 0; f < 8; f++)
        vT[f * VSTRIDE + tid] = pkf16(pv[1][f], pv[0][f]);
    __syncthreads();

    // ---------------- main loop: warp = 16 queries ----------------
    int lane = tid & 31, warp = tid >> 5;
    int g  = lane >> 2;        // 0..7
    int tc = lane & 3;         // 0..3

    int qbase = qt * 256 + warp * 16;
    int q0 = qbase + g;
    int q1 = q0 + 8;

    const float kexp = 1.4426950408889634f * 0.35355339059327373f;
    u32 A0 = cvt_tf32(skf[q0 * KSTRIDE + tc]     * kexp);
    u32 A1 = cvt_tf32(skf[q1 * KSTRIDE + tc]     * kexp);
    u32 A2 = cvt_tf32(skf[q0 * KSTRIDE + tc + 4] * kexp);
    u32 A3 = cvt_tf32(skf[q1 * KSTRIDE + tc + 4] * kexp);

    float o0 = 0.f, o1 = 0.f, o2 = 0.f, o3 = 0.f;
    float e0 = 0.f, e1 = 0.f, e2 = 0.f, e3 = 0.f;
    const u32* sku = (const u32*)skf;
    const u32* vTg = vT + g * VSTRIDE;

#pragma unroll 2
    for (int kb = 0; kb < SS; kb += 16) {
        u32 b10 = sku[(kb + g) * KSTRIDE + tc];
        u32 b11 = sku[(kb + g) * KSTRIDE + tc + 4];
        u32 b20 = sku[(kb + 8 + g) * KSTRIDE + tc];
        u32 b21 = sku[(kb + 8 + g) * KSTRIDE + tc + 4];

        float d10, d11, d12, d13, d20, d21, d22, d23;
        MMA_TF32(d10, d11, d12, d13, A0, A1, A2, A3, b10, b11, 0.f, 0.f, 0.f, 0.f);
        MMA_TF32(d20, d21, d22, d23, A0, A1, A2, A3, b20, b21, 0.f, 0.f, 0.f, 0.f);

        // packed f16 weights: one MUFU op per PAIR of exps; packed result
        // is exactly the f16 m16n8k16 A-fragment (a0..a3), no permutation
        u32 Wa0 = ex2h2(pkf16(d11, d10));   // row g,   keys 2tc,2tc+1
        u32 Wa1 = ex2h2(pkf16(d13, d12));   // row g+8, keys 2tc,2tc+1
        u32 Wa2 = ex2h2(pkf16(d21, d20));   // row g,   keys 8+2tc,8+2tc+1
        u32 Wa3 = ex2h2(pkf16(d23, d22));   // row g+8

        // f16 B fragment: features of key pairs (kb/2+tc) and (kb/2+4+tc)
        int pw = kb >> 1;
        u32 Bv0 = vTg[pw + tc];
        u32 Bv1 = vTg[pw + 4 + tc];

        // AV (K=16: all 16 keys in one MMA) + consistent denominator
        MMA_F16(o0, o1, o2, o3, Wa0, Wa1, Wa2, Wa3, Bv0, Bv1, o0, o1, o2, o3);
        MMA_F16(e0, e1, e2, e3, Wa0, Wa1, Wa2, Wa3, ONES_F16X2, ONES_F16X2,
                e0, e1, e2, e3);
    }

    float i0 = __frcp_rn(e0), i1 = __frcp_rn(e2);

    int tok0 = b * SS + q0;
    int tok1 = tok0 + 8;
    float2* o2p = (float2*)g_attn;
    o2p[tok0 * 32 + h * 4 + tc] = make_float2(o0 * i0, o1 * i0);
    o2p[tok1 * 32 + h * 4 + tc] = make_float2(o2 * i1, o3 * i1);
}

// ---------------------------------------------------------------------------
// Kernel 3: out[token, e] = sum_k attn[token, k] * W[e, k]
// 256 CTAs x 256 thr x 32 tokens; thread = token-pair x e-quad (R14 best).
// ---------------------------------------------------------------------------
__global__ __launch_bounds__(256) void combine_kernel(const float* __restrict__ W,
                                                      float* __restrict__ out) {
    __shared__ float wt[EE * 68];        // wt[k*68+e] = W[e*64+k], padded rows
    __shared__ float rows[32][68];       // 32 token rows, padded

    int tid = threadIdx.x;

    const float4* W4 = (const float4*)W;
    float4 v[4];
#pragma unroll
    for (int j = 0; j < 4; j++) v[j] = W4[tid + j * 256];
#pragma unroll
    for (int j = 0; j < 4; j++) {
        int idx = tid + j * 256;
        int e = idx >> 4, k0 = (idx & 15) * 4;
        wt[(k0 + 0) * 68 + e] = v[j].x;
        wt[(k0 + 1) * 68 + e] = v[j].y;
        wt[(k0 + 2) * 68 + e] = v[j].z;
        wt[(k0 + 3) * 68 + e] = v[j].w;
    }

    int token0 = blockIdx.x * 32;
    const float4* ga4 = (const float4*)g_attn + token0 * 16;
#pragma unroll
    for (int j = 0; j < 2; j++) {
        int i = tid + j * 256;            // 32 tokens x 16 float4 = 512
        int t = i >> 4, kg = i & 15;
        float4 vv = ga4[i];
        rows[t][kg * 4 + 0] = vv.x; rows[t][kg * 4 + 1] = vv.y;
        rows[t][kg * 4 + 2] = vv.z; rows[t][kg * 4 + 3] = vv.w;
    }
    __syncthreads();

    int tp = tid >> 4;      // token pair 0..15 -> tokens 2tp, 2tp+1
    int og = tid & 15;      // e-quad: outputs og*4 .. og*4+3
    const ulonglong2* wt2 = (const ulonglong2*)wt;   // 17 units per row

    u64 a0 = 0, a1 = 0, c0 = 0, c1 = 0;
#pragma unroll
    for (int k = 0; k < EE; k++) {
        ulonglong2 bw = wt2[k * 17 + og];
        float r0 = rows[2 * tp + 0][k];
        float r1 = rows[2 * tp + 1][k];
        u64 rr0 = pk2(r0, r0);
        u64 rr1 = pk2(r1, r1);
        a0 = pfma(rr0, bw.x, a0);
        a1 = pfma(rr0, bw.y, a1);
        c0 = pfma(rr1, bw.x, c0);
        c1 = pfma(rr1, bw.y, c1);
    }
    ulonglong2* o2 = (ulonglong2*)out;
    int t0 = token0 + 2 * tp;
    ulonglong2 r0; r0.x = a0; r0.y = a1;
    ulonglong2 r1; r1.x = c0; r1.y = c1;
    o2[(t0 + 0) * 16 + og] = r0;
    o2[(t0 + 1) * 16 + og] = r1;
}

// ---------------------------------------------------------------------------
extern "C" void kernel_launch(void* const* d_in, const int* in_sizes, int n_in,
                              void* d_out, int out_size) {
    const float* x      = (const float*)d_in[0];   // [8,1024,64]
    const float* theta  = (const float*)d_in[1];   // [8]
    const float* Wc     = (const float*)d_in[2];   // [64,64]
    float* out          = (float*)d_out;           // [8,1024,64]

    cudaFuncSetAttribute(attn_fused, cudaFuncAttributeMaxDynamicSharedMemorySize,
                         ATTN_SMEM_BYTES);

    dim3 agrid(NBH, SS / 256);
    attn_fused<<<agrid, 512, ATTN_SMEM_BYTES>>>(x, theta);

    combine_kernel<<<NTOK / 32, 256>>>(Wc, out);
}